// round 1
// baseline (speedup 1.0000x reference)
#include <cuda_runtime.h>
#include <math.h>

#define FDIM 128
#define NMAX 20000
#define EMAX 320000

// ---------------- scratch (static device globals; no allocation) ------------
__device__ float g_h[NMAX * FDIM];          // silu(q@W1+b1)        [N,128]
__device__ float g_ctx[NMAX * 3 * FDIM];    // ctx                  [N,384]
__device__ int   g_counts[NMAX];
__device__ int   g_rowstart[NMAX + 1];
__device__ int   g_cursor[NMAX];
__device__ int   g_perm[EMAX];

// ---------------- float4 helpers -------------------------------------------
__device__ __forceinline__ float4 f4mul(float4 a, float4 b) {
    return make_float4(a.x*b.x, a.y*b.y, a.z*b.z, a.w*b.w);
}
__device__ __forceinline__ float4 f4fma(float4 a, float4 b, float4 c) {
    return make_float4(fmaf(a.x,b.x,c.x), fmaf(a.y,b.y,c.y),
                       fmaf(a.z,b.z,c.z), fmaf(a.w,b.w,c.w));
}
__device__ __forceinline__ float4 f4fmas(float4 a, float s, float4 c) {
    return make_float4(fmaf(a.x,s,c.x), fmaf(a.y,s,c.y),
                       fmaf(a.z,s,c.z), fmaf(a.w,s,c.w));
}

// ---------------- GEMM1: h = silu(q @ W1 + b1)  [N,128]x[128,128] -----------
// block: 256 threads (ty 0..7 x tx 0..31), tile 32 rows x 128 cols,
// per-thread 4x4 register tile. Dynamic smem: As[128][32] + Ws[128][128].
__global__ void __launch_bounds__(256, 2)
gemm1_silu(const float* __restrict__ q, const float* __restrict__ W1,
           const float* __restrict__ b1, int n) {
    extern __shared__ float smem[];
    float* As = smem;               // [k][r] : 128*32
    float* Ws = smem + FDIM * 32;   // [k][c] : 128*128

    int t  = threadIdx.x;
    int tx = t & 31, ty = t >> 5;
    int row0 = blockIdx.x * 32;

    // load W1 (16384 floats = 4096 float4)
    const float4* W4  = (const float4*)W1;
    float4*       Ws4 = (float4*)Ws;
#pragma unroll
    for (int i = 0; i < 16; i++) Ws4[t + i * 256] = __ldg(&W4[t + i * 256]);

    // load A tile transposed: As[k][r]
    const float4* Q4 = (const float4*)q;
#pragma unroll
    for (int i = 0; i < 4; i++) {
        int idx = t + i * 256;
        int r = idx >> 5, c4 = idx & 31;
        float4 v = (row0 + r < n) ? __ldg(&Q4[(size_t)(row0 + r) * 32 + c4])
                                  : make_float4(0.f, 0.f, 0.f, 0.f);
        As[(c4*4+0)*32 + r] = v.x; As[(c4*4+1)*32 + r] = v.y;
        As[(c4*4+2)*32 + r] = v.z; As[(c4*4+3)*32 + r] = v.w;
    }
    __syncthreads();

    float acc[4][4];
#pragma unroll
    for (int m = 0; m < 4; m++)
#pragma unroll
        for (int c = 0; c < 4; c++) acc[m][c] = 0.f;

#pragma unroll 8
    for (int k = 0; k < FDIM; k++) {
        float4 a = *(const float4*)&As[k*32 + ty*4];
        float4 w = *(const float4*)&Ws[k*FDIM + tx*4];
        float am[4] = {a.x, a.y, a.z, a.w};
#pragma unroll
        for (int m = 0; m < 4; m++) {
            acc[m][0] = fmaf(am[m], w.x, acc[m][0]);
            acc[m][1] = fmaf(am[m], w.y, acc[m][1]);
            acc[m][2] = fmaf(am[m], w.z, acc[m][2]);
            acc[m][3] = fmaf(am[m], w.w, acc[m][3]);
        }
    }

    float4 bb = __ldg(&((const float4*)b1)[tx]);
    float bv[4] = {bb.x, bb.y, bb.z, bb.w};
#pragma unroll
    for (int m = 0; m < 4; m++) {
        int row = row0 + ty*4 + m;
        if (row < n) {
            float4 o;
            float v0 = acc[m][0] + bv[0]; o.x = v0 / (1.f + __expf(-v0));
            float v1 = acc[m][1] + bv[1]; o.y = v1 / (1.f + __expf(-v1));
            float v2 = acc[m][2] + bv[2]; o.z = v2 / (1.f + __expf(-v2));
            float v3 = acc[m][3] + bv[3]; o.w = v3 / (1.f + __expf(-v3));
            ((float4*)g_h)[(size_t)row * 32 + tx] = o;
        }
    }
}

// ---------------- GEMM2: ctx = h @ W2 + b2  [N,128]x[128,384] ---------------
// blockIdx.y = column tile (0..2), each 128 cols of W2.
__global__ void __launch_bounds__(256, 2)
gemm2(const float* __restrict__ W2, const float* __restrict__ b2, int n) {
    extern __shared__ float smem[];
    float* As = smem;
    float* Ws = smem + FDIM * 32;

    int t  = threadIdx.x;
    int tx = t & 31, ty = t >> 5;
    int row0 = blockIdx.x * 32;
    int ct   = blockIdx.y;          // column tile

    // load W2 column tile: Ws[k][c] = W2[k*384 + ct*128 + c]
    const float4* W4  = (const float4*)W2;   // 96 float4 per k-row
#pragma unroll
    for (int i = 0; i < 16; i++) {
        int idx = t + i * 256;          // 0..4095
        int k = idx >> 5, c4 = idx & 31;
        ((float4*)Ws)[idx] = __ldg(&W4[(size_t)k * 96 + ct * 32 + c4]);
    }

    const float4* H4 = (const float4*)g_h;
#pragma unroll
    for (int i = 0; i < 4; i++) {
        int idx = t + i * 256;
        int r = idx >> 5, c4 = idx & 31;
        float4 v = (row0 + r < n) ? H4[(size_t)(row0 + r) * 32 + c4]
                                  : make_float4(0.f, 0.f, 0.f, 0.f);
        As[(c4*4+0)*32 + r] = v.x; As[(c4*4+1)*32 + r] = v.y;
        As[(c4*4+2)*32 + r] = v.z; As[(c4*4+3)*32 + r] = v.w;
    }
    __syncthreads();

    float acc[4][4];
#pragma unroll
    for (int m = 0; m < 4; m++)
#pragma unroll
        for (int c = 0; c < 4; c++) acc[m][c] = 0.f;

#pragma unroll 8
    for (int k = 0; k < FDIM; k++) {
        float4 a = *(const float4*)&As[k*32 + ty*4];
        float4 w = *(const float4*)&Ws[k*FDIM + tx*4];
        float am[4] = {a.x, a.y, a.z, a.w};
#pragma unroll
        for (int m = 0; m < 4; m++) {
            acc[m][0] = fmaf(am[m], w.x, acc[m][0]);
            acc[m][1] = fmaf(am[m], w.y, acc[m][1]);
            acc[m][2] = fmaf(am[m], w.z, acc[m][2]);
            acc[m][3] = fmaf(am[m], w.w, acc[m][3]);
        }
    }

    float4 bb = __ldg(&((const float4*)b2)[ct * 32 + tx]);
#pragma unroll
    for (int m = 0; m < 4; m++) {
        int row = row0 + ty*4 + m;
        if (row < n) {
            float4 o = make_float4(acc[m][0]+bb.x, acc[m][1]+bb.y,
                                   acc[m][2]+bb.z, acc[m][3]+bb.w);
            ((float4*)g_ctx)[(size_t)row * 96 + ct * 32 + tx] = o;
        }
    }
}

// ---------------- CSR build --------------------------------------------------
__global__ void zero_counts(int n) {
    int i = blockIdx.x * blockDim.x + threadIdx.x;
    if (i < n) g_counts[i] = 0;
}

__global__ void histogram(const int* __restrict__ idx_i, int E) {
    int e = blockIdx.x * blockDim.x + threadIdx.x;
    if (e < E) atomicAdd(&g_counts[idx_i[e]], 1);
}

// single-block exclusive scan over g_counts -> g_rowstart, g_cursor
__global__ void scan1024(int n) {
    __shared__ int sh[1024];
    __shared__ int carry;
    int t = threadIdx.x;
    if (t == 0) carry = 0;
    __syncthreads();
    for (int base = 0; base < n; base += 1024) {
        int idx = base + t;
        int v = (idx < n) ? g_counts[idx] : 0;
        sh[t] = v;
        __syncthreads();
#pragma unroll
        for (int off = 1; off < 1024; off <<= 1) {
            int tv = (t >= off) ? sh[t - off] : 0;
            __syncthreads();
            sh[t] += tv;
            __syncthreads();
        }
        int excl = sh[t] - v + carry;
        if (idx < n) { g_rowstart[idx] = excl; g_cursor[idx] = excl; }
        __syncthreads();
        if (t == 0) carry += sh[1023];
        __syncthreads();
    }
    if (t == 0) g_rowstart[n] = carry;
}

__global__ void scatter(const int* __restrict__ idx_i, int E) {
    int e = blockIdx.x * blockDim.x + threadIdx.x;
    if (e < E) {
        int pos = atomicAdd(&g_cursor[idx_i[e]], 1);
        g_perm[pos] = e;
    }
}

// ---------------- aggregation: one warp per destination node ----------------
__global__ void __launch_bounds__(256)
aggregate(const float* __restrict__ q, const float* __restrict__ mu,
          const float* __restrict__ W_ij, const float* __restrict__ dir_ij,
          const int* __restrict__ idx_j, float* __restrict__ out, int n) {
    int warp = (blockIdx.x * blockDim.x + threadIdx.x) >> 5;
    int lane = threadIdx.x & 31;
    if (warp >= n) return;
    int node = warp;

    const float4* Q4  = (const float4*)q;
    const float4* MU4 = (const float4*)mu;
    const float4* W4  = (const float4*)W_ij;
    const float4* C4  = (const float4*)g_ctx;

    float4 aq  = Q4[(size_t)node * 32 + lane];
    float4 am0 = MU4[(size_t)node * 96 + lane];
    float4 am1 = MU4[(size_t)node * 96 + 32 + lane];
    float4 am2 = MU4[(size_t)node * 96 + 64 + lane];

    int start = g_rowstart[node];
    int end   = g_rowstart[node + 1];

    for (int p = start; p < end; p++) {
        int e = g_perm[p];
        int j = __ldg(&idx_j[e]);
        float dx = __ldg(&dir_ij[e * 3 + 0]);
        float dy = __ldg(&dir_ij[e * 3 + 1]);
        float dz = __ldg(&dir_ij[e * 3 + 2]);

        size_t bw = (size_t)e * 96;
        float4 w0 = __ldg(&W4[bw + lane]);
        float4 w1 = __ldg(&W4[bw + 32 + lane]);
        float4 w2 = __ldg(&W4[bw + 64 + lane]);

        size_t bc = (size_t)j * 96;
        float4 c0 = __ldg(&C4[bc + lane]);
        float4 c1 = __ldg(&C4[bc + 32 + lane]);
        float4 c2 = __ldg(&C4[bc + 64 + lane]);

        float4 mj0 = __ldg(&MU4[bc + lane]);
        float4 mj1 = __ldg(&MU4[bc + 32 + lane]);
        float4 mj2 = __ldg(&MU4[bc + 64 + lane]);

        aq = f4fma(w0, c0, aq);
        float4 r  = f4mul(w1, c1);
        float4 mm = f4mul(w2, c2);
        am0 = f4fma(mm, mj0, f4fmas(r, dx, am0));
        am1 = f4fma(mm, mj1, f4fmas(r, dy, am1));
        am2 = f4fma(mm, mj2, f4fmas(r, dz, am2));
    }

    float4* outq  = (float4*)out;
    float4* outmu = (float4*)(out + (size_t)n * FDIM);
    outq[(size_t)node * 32 + lane] = aq;
    outmu[(size_t)node * 96 + lane]      = am0;
    outmu[(size_t)node * 96 + 32 + lane] = am1;
    outmu[(size_t)node * 96 + 64 + lane] = am2;
}

// ---------------- launch -----------------------------------------------------
extern "C" void kernel_launch(void* const* d_in, const int* in_sizes, int n_in,
                              void* d_out, int out_size) {
    const float* q      = (const float*)d_in[0];
    const float* mu     = (const float*)d_in[1];
    const float* W_ij   = (const float*)d_in[2];
    const float* dir_ij = (const float*)d_in[3];
    const float* W1     = (const float*)d_in[4];
    const float* b1     = (const float*)d_in[5];
    const float* W2     = (const float*)d_in[6];
    const float* b2     = (const float*)d_in[7];
    const int*   idx_i  = (const int*)d_in[8];
    const int*   idx_j  = (const int*)d_in[9];

    int n = in_sizes[0] / FDIM;       // 20000
    int E = in_sizes[8];              // 320000

    const int GEMM_SMEM = (FDIM * 32 + FDIM * FDIM) * (int)sizeof(float); // 80KB
    cudaFuncSetAttribute(gemm1_silu, cudaFuncAttributeMaxDynamicSharedMemorySize, GEMM_SMEM);
    cudaFuncSetAttribute(gemm2,      cudaFuncAttributeMaxDynamicSharedMemorySize, GEMM_SMEM);

    int gemm_blocks = (n + 31) / 32;
    gemm1_silu<<<gemm_blocks, 256, GEMM_SMEM>>>(q, W1, b1, n);
    gemm2<<<dim3(gemm_blocks, 3), 256, GEMM_SMEM>>>(W2, b2, n);

    zero_counts<<<(n + 255) / 256, 256>>>(n);
    histogram<<<(E + 255) / 256, 256>>>(idx_i, E);
    scan1024<<<1, 1024>>>(n);
    scatter<<<(E + 255) / 256, 256>>>(idx_i, E);

    int agg_blocks = (n * 32 + 255) / 256;
    aggregate<<<agg_blocks, 256>>>(q, mu, W_ij, dir_ij, idx_j, (float*)d_out, n);
}